// round 8
// baseline (speedup 1.0000x reference)
#include <cuda_runtime.h>
#include <cuda_bf16.h>
#include <cstdint>
#include <math.h>

#define D_MODEL 1024
#define N_HEAD  16
#define D_K     64
#define BATCH   2
#define SEQ     2048
#define MROWS   (BATCH * SEQ)   // 4096
#define WELEM   (D_MODEL * D_MODEL)
#define XELEM   (MROWS * D_MODEL)

// ===================== scratch (allocation-free: device globals) ============
__device__ __nv_bfloat16 g_W4hi[4 * WELEM];   // 4 transposed-split weights
__device__ __nv_bfloat16 g_W4lo[4 * WELEM];
__device__ __nv_bfloat16 g_X3hi[3 * XELEM];   // split q,k,v inputs
__device__ __nv_bfloat16 g_X3lo[3 * XELEM];
__device__ __nv_bfloat16 g_Qhi[XELEM], g_Qlo[XELEM];
__device__ __nv_bfloat16 g_Khi[XELEM], g_Klo[XELEM];
__device__ __nv_bfloat16 g_Vhi[XELEM], g_Vlo[XELEM];
__device__ __nv_bfloat16 g_Ahi[XELEM], g_Alo[XELEM];   // attention output (split)

// ===================== helpers ==============================================
__device__ __forceinline__ uint32_t smem_u32_of(const void* p) {
    uint32_t a;
    asm("{ .reg .u64 t; cvta.to.shared.u64 t, %1; cvt.u32.u64 %0, t; }"
        : "=r"(a) : "l"(p));
    return a;
}
__device__ __forceinline__ void ldmx4(uint32_t addr, uint32_t& r0, uint32_t& r1,
                                      uint32_t& r2, uint32_t& r3) {
    asm volatile("ldmatrix.sync.aligned.m8n8.x4.shared.b16 {%0,%1,%2,%3}, [%4];"
                 : "=r"(r0), "=r"(r1), "=r"(r2), "=r"(r3) : "r"(addr));
}
__device__ __forceinline__ void ldmx4t(uint32_t addr, uint32_t& r0, uint32_t& r1,
                                       uint32_t& r2, uint32_t& r3) {
    asm volatile("ldmatrix.sync.aligned.m8n8.x4.trans.shared.b16 {%0,%1,%2,%3}, [%4];"
                 : "=r"(r0), "=r"(r1), "=r"(r2), "=r"(r3) : "r"(addr));
}
// NOTE: NOT volatile — pure register computation; lets ptxas interleave
// independent accumulator chains (the R7 bottleneck).
__device__ __forceinline__ void mma16816(float* c, const uint32_t* a,
                                         uint32_t b0, uint32_t b1) {
    asm("mma.sync.aligned.m16n8k16.row.col.f32.bf16.bf16.f32 "
        "{%0,%1,%2,%3}, {%4,%5,%6,%7}, {%8,%9}, {%0,%1,%2,%3};"
        : "+f"(c[0]), "+f"(c[1]), "+f"(c[2]), "+f"(c[3])
        : "r"(a[0]), "r"(a[1]), "r"(a[2]), "r"(a[3]), "r"(b0), "r"(b1));
}
__device__ __forceinline__ uint32_t pack_bf16(float x, float y) {
    __nv_bfloat162 t = __floats2bfloat162_rn(x, y);
    return *(uint32_t*)&t;
}
__device__ __forceinline__ void cp16(uint32_t dst, const void* src) {
    asm volatile("cp.async.cg.shared.global [%0], [%1], 16;"
                 :: "r"(dst), "l"(src) : "memory");
}
#define CP_COMMIT()  asm volatile("cp.async.commit_group;" ::: "memory")
#define CP_WAIT1()   asm volatile("cp.async.wait_group 1;" ::: "memory")

// ===================== fused conversions ====================================
__global__ __launch_bounds__(256) void split_all(
    const float* __restrict__ x0, const float* __restrict__ x1,
    const float* __restrict__ x2)
{
    const int which = blockIdx.y;
    const float* x = (which == 0) ? x0 : (which == 1) ? x1 : x2;
    __nv_bfloat16* hi = g_X3hi + (size_t)which * XELEM;
    __nv_bfloat16* lo = g_X3lo + (size_t)which * XELEM;
    const int i = blockIdx.x * 256 + threadIdx.x;
    float4 v = ((const float4*)x)[i];
    __nv_bfloat16 h0 = __float2bfloat16_rn(v.x);
    __nv_bfloat16 h1 = __float2bfloat16_rn(v.y);
    __nv_bfloat16 h2 = __float2bfloat16_rn(v.z);
    __nv_bfloat16 h3 = __float2bfloat16_rn(v.w);
    ((__nv_bfloat162*)hi)[i * 2 + 0] = __nv_bfloat162(h0, h1);
    ((__nv_bfloat162*)hi)[i * 2 + 1] = __nv_bfloat162(h2, h3);
    ((__nv_bfloat162*)lo)[i * 2 + 0] = __nv_bfloat162(
        __float2bfloat16_rn(v.x - __bfloat162float(h0)),
        __float2bfloat16_rn(v.y - __bfloat162float(h1)));
    ((__nv_bfloat162*)lo)[i * 2 + 1] = __nv_bfloat162(
        __float2bfloat16_rn(v.z - __bfloat162float(h2)),
        __float2bfloat16_rn(v.w - __bfloat162float(h3)));
}

__global__ __launch_bounds__(256) void wsplit_all(
    const float* __restrict__ w0, const float* __restrict__ w1,
    const float* __restrict__ w2, const float* __restrict__ w3)
{
    __shared__ float t[32][33];
    const int z = blockIdx.z;
    const float* W = (z == 0) ? w0 : (z == 1) ? w1 : (z == 2) ? w2 : w3;
    __nv_bfloat16* hiT = g_W4hi + (size_t)z * WELEM;
    __nv_bfloat16* loT = g_W4lo + (size_t)z * WELEM;
    const int nBase = blockIdx.x * 32, kBase = blockIdx.y * 32;
    const int tx = threadIdx.x, ty = threadIdx.y;
    #pragma unroll
    for (int r = 0; r < 4; r++)
        t[ty + 8 * r][tx] = W[(size_t)(kBase + ty + 8 * r) * D_MODEL + nBase + tx];
    __syncthreads();
    #pragma unroll
    for (int r = 0; r < 4; r++) {
        float v = t[tx][ty + 8 * r];
        __nv_bfloat16 h = __float2bfloat16_rn(v);
        size_t o = (size_t)(nBase + ty + 8 * r) * D_MODEL + kBase + tx;
        hiT[o] = h;
        loT[o] = __float2bfloat16_rn(v - __bfloat162float(h));
    }
}

// ===================== HMMA split-bf16 GEMM core ============================
#define GBM 128
#define GBN 128
#define GBK 32
#define G_TILE_B 16384
#define G_STG_B  (2 * G_TILE_B)
#define G_SMEM   (3 * G_STG_B)
#define NCH (D_MODEL / GBK)

__device__ __forceinline__ void gemm_core(
    const __nv_bfloat16* __restrict__ Ahi, const __nv_bfloat16* __restrict__ Alo,
    const __nv_bfloat16* __restrict__ Bhi, const __nv_bfloat16* __restrict__ Blo,
    const float* __restrict__ bias, float* __restrict__ C,
    __nv_bfloat16* __restrict__ Chi, __nv_bfloat16* __restrict__ Clo,
    float scale, char* smem)
{
    const uint32_t dsb = smem_u32_of(smem);
    const int tid = threadIdx.x;
    const int wid = tid >> 5;
    const int lane = tid & 31;
    const int warp_m = wid & 1;
    const int warp_n = wid >> 1;
    const size_t rBase = (size_t)blockIdx.y * GBM;
    const size_t nBase = (size_t)blockIdx.x * GBN;

    float acc[4][4][4] = {};

    const int lr = tid >> 2;
    const int lc = tid & 3;
    const int gcol = lc * 8;

    auto issue = [&](int ck, int stg) {
        const uint32_t sb = dsb + (uint32_t)(stg * G_STG_B);
        const int k0 = ck * GBK;
        #pragma unroll
        for (int it = 0; it < 2; it++) {
            const int r = lr + it * 64;
            const uint32_t ph = (uint32_t)(((lc ^ (r & 7)) * 16));
            const uint32_t ro = (uint32_t)(r * 128);
            const size_t gA = (rBase + r) * D_MODEL + k0 + gcol;
            const size_t gB = (nBase + r) * D_MODEL + k0 + gcol;
            cp16(sb + ro + ph, Ahi + gA);
            cp16(sb + ro + (ph ^ 64), Alo + gA);
            cp16(sb + G_TILE_B + ro + ph, Bhi + gB);
            cp16(sb + G_TILE_B + ro + (ph ^ 64), Blo + gB);
        }
    };

    issue(0, 0); CP_COMMIT();
    issue(1, 1); CP_COMMIT();

    const int lrow = lane & 15;
    const uint32_t phys0 = (uint32_t)((((lane >> 4) ^ (lane & 7)) * 16));
    uint32_t aB[4], bB[2];
    #pragma unroll
    for (int mi = 0; mi < 4; mi++)
        aB[mi] = dsb + (uint32_t)((warp_m * 64 + mi * 16 + lrow) * 128) + phys0;
    #pragma unroll
    for (int p = 0; p < 2; p++)
        bB[p] = dsb + G_TILE_B + (uint32_t)((warp_n * 32 + p * 16 + lrow) * 128) + phys0;

    int sC = 0, sI = 2;
    for (int c = 0; c < NCH; c++) {
        CP_WAIT1();
        __syncthreads();
        if (c + 2 < NCH) issue(c + 2, sI);
        CP_COMMIT();
        sI = (sI == 2) ? 0 : sI + 1;

        const uint32_t so = (uint32_t)(sC * G_STG_B);
        sC = (sC == 2) ? 0 : sC + 1;

        #pragma unroll
        for (int kk = 0; kk < 2; kk++) {
            const uint32_t xk = (uint32_t)(kk * 32);
            uint32_t bh[8], bl[8];
            #pragma unroll
            for (int p = 0; p < 2; p++) {
                const uint32_t ad = (bB[p] + so) ^ xk;
                uint32_t r0, r1, r2, r3;
                ldmx4(ad, r0, r1, r2, r3);
                bh[p * 4 + 0] = r0; bh[p * 4 + 1] = r2;
                bh[p * 4 + 2] = r1; bh[p * 4 + 3] = r3;
                ldmx4(ad ^ 64, r0, r1, r2, r3);
                bl[p * 4 + 0] = r0; bl[p * 4 + 1] = r2;
                bl[p * 4 + 2] = r1; bl[p * 4 + 3] = r3;
            }
            #pragma unroll
            for (int mi = 0; mi < 4; mi++) {
                const uint32_t aa = (aB[mi] + so) ^ xk;
                uint32_t ah[4], al[4];
                ldmx4(aa, ah[0], ah[1], ah[2], ah[3]);
                ldmx4(aa ^ 64, al[0], al[1], al[2], al[3]);
                // product-major: 4 independent acc chains per pass
                #pragma unroll
                for (int ni = 0; ni < 4; ni++)
                    mma16816(acc[mi][ni], ah,
                             bh[(ni >> 1) * 4 + (ni & 1) * 2],
                             bh[(ni >> 1) * 4 + (ni & 1) * 2 + 1]);
                #pragma unroll
                for (int ni = 0; ni < 4; ni++)
                    mma16816(acc[mi][ni], ah,
                             bl[(ni >> 1) * 4 + (ni & 1) * 2],
                             bl[(ni >> 1) * 4 + (ni & 1) * 2 + 1]);
                #pragma unroll
                for (int ni = 0; ni < 4; ni++)
                    mma16816(acc[mi][ni], al,
                             bh[(ni >> 1) * 4 + (ni & 1) * 2],
                             bh[(ni >> 1) * 4 + (ni & 1) * 2 + 1]);
            }
        }
    }

    const int crow = lane >> 2;
    const int ccol = (lane & 3) * 2;
    #pragma unroll
    for (int mi = 0; mi < 4; mi++) {
        #pragma unroll
        for (int ni = 0; ni < 4; ni++) {
            const size_t row0 = rBase + warp_m * 64 + mi * 16 + crow;
            const size_t col = nBase + warp_n * 32 + ni * 8 + ccol;
            const float b0 = bias[col], b1 = bias[col + 1];
            float v00 = acc[mi][ni][0] + b0, v01 = acc[mi][ni][1] + b1;
            float v10 = acc[mi][ni][2] + b0, v11 = acc[mi][ni][3] + b1;
            if (Chi) {
                v00 *= scale; v01 *= scale; v10 *= scale; v11 *= scale;
                __nv_bfloat16 h00 = __float2bfloat16_rn(v00);
                __nv_bfloat16 h01 = __float2bfloat16_rn(v01);
                __nv_bfloat16 h10 = __float2bfloat16_rn(v10);
                __nv_bfloat16 h11 = __float2bfloat16_rn(v11);
                *(__nv_bfloat162*)(Chi + row0 * D_MODEL + col) = __nv_bfloat162(h00, h01);
                *(__nv_bfloat162*)(Chi + (row0 + 8) * D_MODEL + col) = __nv_bfloat162(h10, h11);
                *(__nv_bfloat162*)(Clo + row0 * D_MODEL + col) = __nv_bfloat162(
                    __float2bfloat16_rn(v00 - __bfloat162float(h00)),
                    __float2bfloat16_rn(v01 - __bfloat162float(h01)));
                *(__nv_bfloat162*)(Clo + (row0 + 8) * D_MODEL + col) = __nv_bfloat162(
                    __float2bfloat16_rn(v10 - __bfloat162float(h10)),
                    __float2bfloat16_rn(v11 - __bfloat162float(h11)));
            } else {
                *(float2*)(C + row0 * D_MODEL + col) = make_float2(v00, v01);
                *(float2*)(C + (row0 + 8) * D_MODEL + col) = make_float2(v10, v11);
            }
        }
    }
}

__global__ __launch_bounds__(256, 2) void gemm_qkv(
    const float* __restrict__ b_q, const float* __restrict__ b_k,
    const float* __restrict__ b_v)
{
    extern __shared__ __align__(128) char smem_q[];
    const int z = blockIdx.z;
    const __nv_bfloat16* Ahi = g_X3hi + (size_t)z * XELEM;
    const __nv_bfloat16* Alo = g_X3lo + (size_t)z * XELEM;
    const __nv_bfloat16* Bhi = g_W4hi + (size_t)z * WELEM;
    const __nv_bfloat16* Blo = g_W4lo + (size_t)z * WELEM;
    const float* bias = (z == 0) ? b_q : (z == 1) ? b_k : b_v;
    __nv_bfloat16* Chi = (z == 0) ? g_Qhi : (z == 1) ? g_Khi : g_Vhi;
    __nv_bfloat16* Clo = (z == 0) ? g_Qlo : (z == 1) ? g_Klo : g_Vlo;
    const float scale = (z == 0) ? 0.125f : 1.0f;
    gemm_core(Ahi, Alo, Bhi, Blo, bias, nullptr, Chi, Clo, scale, smem_q);
}

__global__ __launch_bounds__(256, 2) void gemm_o(
    const float* __restrict__ b_o, float* __restrict__ out)
{
    extern __shared__ __align__(128) char smem_o[];
    gemm_core(g_Ahi, g_Alo, g_W4hi + 3 * (size_t)WELEM, g_W4lo + 3 * (size_t)WELEM,
              b_o, out, nullptr, nullptr, 1.0f, smem_o);
}

// ===================== tensor-core flash attention ==========================
// Key tile 32, 3-stage cp.async, 1 sync/iter, Q fragments from GMEM,
// 2 CTAs/SM, MMA chains interleaved across accumulators.
#define AKT 32
#define ASTR 72
#define AT_TILE (AKT * ASTR)               // 2304 elems
#define AT_STG_B (4 * AT_TILE * 2)         // 18432 bytes (Kh,Kl,Vh,Vl)
#define ATTN_SMEM (3 * AT_STG_B)           // 55296
#define NKT (SEQ / AKT)                    // 64

__global__ __launch_bounds__(256, 2) void attn_mma()
{
    extern __shared__ __align__(128) __nv_bfloat16 as_[];
    const uint32_t asb = smem_u32_of(as_);

    const int qt = blockIdx.x;
    const int hb = blockIdx.y;
    const int h = hb / BATCH;
    const int b = hb % BATCH;
    const int tid = threadIdx.x;
    const int wid = tid >> 5;
    const int lane = tid & 31;

    const size_t headOff = (size_t)b * SEQ * D_MODEL + (size_t)h * D_K;
    const __nv_bfloat16* Qh = g_Qhi + headOff;
    const __nv_bfloat16* Ql = g_Qlo + headOff;
    const __nv_bfloat16* Kh = g_Khi + headOff;
    const __nv_bfloat16* Kl = g_Klo + headOff;
    const __nv_bfloat16* Vh = g_Vhi + headOff;
    const __nv_bfloat16* Vl = g_Vlo + headOff;

    const int ldr = tid >> 3;
    const int ldc8 = (tid & 7) * 8;
    auto kvissue = [&](int kt, int stg) {
        const uint32_t sb = asb + (uint32_t)(stg * AT_STG_B);
        const size_t g = (size_t)(kt * AKT + ldr) * D_MODEL + ldc8;
        const uint32_t so = (uint32_t)((ldr * ASTR + ldc8) * 2);
        cp16(sb + 0 * AT_TILE * 2 + so, Kh + g);
        cp16(sb + 1 * AT_TILE * 2 + so, Kl + g);
        cp16(sb + 2 * AT_TILE * 2 + so, Vh + g);
        cp16(sb + 3 * AT_TILE * 2 + so, Vl + g);
    };

    kvissue(0, 0); CP_COMMIT();
    kvissue(1, 1); CP_COMMIT();

    // ---- Q fragments straight from GMEM in mma A-layout ----
    uint32_t qh[4][4], ql[4][4];
    {
        const int fr = lane >> 2;
        const int fc = (lane & 3) * 2;
        const size_t r0 = (size_t)(qt * 128 + wid * 16 + fr) * D_MODEL;
        const size_t r1 = r0 + 8 * D_MODEL;
        #pragma unroll
        for (int kt = 0; kt < 4; kt++) {
            const int c = kt * 16 + fc;
            qh[kt][0] = *(const uint32_t*)(Qh + r0 + c);
            qh[kt][1] = *(const uint32_t*)(Qh + r1 + c);
            qh[kt][2] = *(const uint32_t*)(Qh + r0 + c + 8);
            qh[kt][3] = *(const uint32_t*)(Qh + r1 + c + 8);
            ql[kt][0] = *(const uint32_t*)(Ql + r0 + c);
            ql[kt][1] = *(const uint32_t*)(Ql + r1 + c);
            ql[kt][2] = *(const uint32_t*)(Ql + r0 + c + 8);
            ql[kt][3] = *(const uint32_t*)(Ql + r1 + c + 8);
        }
    }

    float m0 = -1e30f, m1 = -1e30f, l0 = 0.0f, l1 = 0.0f;
    float o[8][4] = {};

    const uint32_t lof = (uint32_t)(((lane & 15) * ASTR + (lane >> 4) * 8) * 2);
    const uint32_t kB0 = asb + lof;
    const uint32_t kL0 = kB0 + AT_TILE * 2;
    const uint32_t vB0 = kB0 + 2 * AT_TILE * 2;
    const uint32_t vL0 = kB0 + 3 * AT_TILE * 2;

    int sC = 0, sI = 2;
    for (int kt0 = 0; kt0 < NKT; kt0++) {
        CP_WAIT1();
        __syncthreads();
        if (kt0 + 2 < NKT) kvissue(kt0 + 2, sI);
        CP_COMMIT();
        sI = (sI == 2) ? 0 : sI + 1;
        const uint32_t so = (uint32_t)(sC * AT_STG_B);
        sC = (sC == 2) ? 0 : sC + 1;

        // ---- S = Q K^T, MMAs interleaved across sc[0..3] ----
        float sc[4][4] = {};
        #pragma unroll
        for (int kt = 0; kt < 4; kt++) {
            uint32_t ka[2][4], kx[2][4];
            #pragma unroll
            for (int np = 0; np < 2; np++) {
                const uint32_t off = (uint32_t)(np * 16 * ASTR * 2 + kt * 32) + so;
                ldmx4(kB0 + off, ka[np][0], ka[np][1], ka[np][2], ka[np][3]);
                ldmx4(kL0 + off, kx[np][0], kx[np][1], kx[np][2], kx[np][3]);
            }
            mma16816(sc[0], qh[kt], ka[0][0], ka[0][2]);
            mma16816(sc[1], qh[kt], ka[0][1], ka[0][3]);
            mma16816(sc[2], qh[kt], ka[1][0], ka[1][2]);
            mma16816(sc[3], qh[kt], ka[1][1], ka[1][3]);
            mma16816(sc[0], ql[kt], ka[0][0], ka[0][2]);
            mma16816(sc[1], ql[kt], ka[0][1], ka[0][3]);
            mma16816(sc[2], ql[kt], ka[1][0], ka[1][2]);
            mma16816(sc[3], ql[kt], ka[1][1], ka[1][3]);
            mma16816(sc[0], qh[kt], kx[0][0], kx[0][2]);
            mma16816(sc[1], qh[kt], kx[0][1], kx[0][3]);
            mma16816(sc[2], qh[kt], kx[1][0], kx[1][2]);
            mma16816(sc[3], qh[kt], kx[1][1], kx[1][3]);
        }

        // ---- online softmax ----
        float mx0 = -1e30f, mx1 = -1e30f;
        #pragma unroll
        for (int nt = 0; nt < 4; nt++) {
            mx0 = fmaxf(mx0, fmaxf(sc[nt][0], sc[nt][1]));
            mx1 = fmaxf(mx1, fmaxf(sc[nt][2], sc[nt][3]));
        }
        mx0 = fmaxf(mx0, __shfl_xor_sync(0xffffffffu, mx0, 1));
        mx0 = fmaxf(mx0, __shfl_xor_sync(0xffffffffu, mx0, 2));
        mx1 = fmaxf(mx1, __shfl_xor_sync(0xffffffffu, mx1, 1));
        mx1 = fmaxf(mx1, __shfl_xor_sync(0xffffffffu, mx1, 2));
        const float m0n = fmaxf(m0, mx0), m1n = fmaxf(m1, mx1);
        const float a0 = __expf(m0 - m0n), a1 = __expf(m1 - m1n);
        float rs0 = 0.0f, rs1 = 0.0f;
        #pragma unroll
        for (int nt = 0; nt < 4; nt++) {
            sc[nt][0] = __expf(sc[nt][0] - m0n);
            sc[nt][1] = __expf(sc[nt][1] - m0n);
            sc[nt][2] = __expf(sc[nt][2] - m1n);
            sc[nt][3] = __expf(sc[nt][3] - m1n);
            rs0 += sc[nt][0] + sc[nt][1];
            rs1 += sc[nt][2] + sc[nt][3];
        }
        #pragma unroll
        for (int nt = 0; nt < 8; nt++) {
            o[nt][0] *= a0; o[nt][1] *= a0;
            o[nt][2] *= a1; o[nt][3] *= a1;
        }
        rs0 += __shfl_xor_sync(0xffffffffu, rs0, 1);
        rs0 += __shfl_xor_sync(0xffffffffu, rs0, 2);
        rs1 += __shfl_xor_sync(0xffffffffu, rs1, 1);
        rs1 += __shfl_xor_sync(0xffffffffu, rs1, 2);
        l0 = l0 * a0 + rs0;
        l1 = l1 * a1 + rs1;
        m0 = m0n; m1 = m1n;

        // ---- split P (16x32) into hi/lo fragments ----
        uint32_t ph[2][4], pl[2][4];
        #pragma unroll
        for (int kt = 0; kt < 2; kt++) {
            const float* sa = sc[2 * kt];
            const float* sb2 = sc[2 * kt + 1];
            float hv;
            float la0, la1, la2, la3, lb0, lb1, lb2, lb3;
            hv = __bfloat162float(__float2bfloat16_rn(sa[0])); la0 = sa[0] - hv;
            hv = __bfloat162float(__float2bfloat16_rn(sa[1])); la1 = sa[1] - hv;
            hv = __bfloat162float(__float2bfloat16_rn(sa[2])); la2 = sa[2] - hv;
            hv = __bfloat162float(__float2bfloat16_rn(sa[3])); la3 = sa[3] - hv;
            hv = __bfloat162float(__float2bfloat16_rn(sb2[0])); lb0 = sb2[0] - hv;
            hv = __bfloat162float(__float2bfloat16_rn(sb2[1])); lb1 = sb2[1] - hv;
            hv = __bfloat162float(__float2bfloat16_rn(sb2[2])); lb2 = sb2[2] - hv;
            hv = __bfloat162float(__float2bfloat16_rn(sb2[3])); lb3 = sb2[3] - hv;
            ph[kt][0] = pack_bf16(sa[0], sa[1]);
            ph[kt][1] = pack_bf16(sa[2], sa[3]);
            ph[kt][2] = pack_bf16(sb2[0], sb2[1]);
            ph[kt][3] = pack_bf16(sb2[2], sb2[3]);
            pl[kt][0] = pack_bf16(la0, la1);
            pl[kt][1] = pack_bf16(la2, la3);
            pl[kt][2] = pack_bf16(lb0, lb1);
            pl[kt][3] = pack_bf16(lb2, lb3);
        }

        // ---- O += P @ V, MMAs interleaved across o[4p..4p+3] ----
        #pragma unroll
        for (int kt = 0; kt < 2; kt++) {
            #pragma unroll
            for (int npp = 0; npp < 2; npp++) {
                uint32_t va[2][4], vx[2][4];
                #pragma unroll
                for (int j = 0; j < 2; j++) {
                    const int np = npp * 2 + j;
                    const uint32_t off = (uint32_t)((kt * 16 * ASTR + np * 16) * 2) + so;
                    ldmx4t(vB0 + off, va[j][0], va[j][1], va[j][2], va[j][3]);
                    ldmx4t(vL0 + off, vx[j][0], vx[j][1], vx[j][2], vx[j][3]);
                }
                float* o0 = o[npp * 4 + 0];
                float* o1 = o[npp * 4 + 1];
                float* o2 = o[npp * 4 + 2];
                float* o3 = o[npp * 4 + 3];
                mma16816(o0, ph[kt], va[0][0], va[0][1]);
                mma16816(o1, ph[kt], va[0][2], va[0][3]);
                mma16816(o2, ph[kt], va[1][0], va[1][1]);
                mma16816(o3, ph[kt], va[1][2], va[1][3]);
                mma16816(o0, pl[kt], va[0][0], va[0][1]);
                mma16816(o1, pl[kt], va[0][2], va[0][3]);
                mma16816(o2, pl[kt], va[1][0], va[1][1]);
                mma16816(o3, pl[kt], va[1][2], va[1][3]);
                mma16816(o0, ph[kt], vx[0][0], vx[0][1]);
                mma16816(o1, ph[kt], vx[0][2], vx[0][3]);
                mma16816(o2, ph[kt], vx[1][0], vx[1][1]);
                mma16816(o3, ph[kt], vx[1][2], vx[1][3]);
            }
        }
    }

    // ---- epilogue: normalize, split, write for the O-projection ----
    const float inv0 = 1.0f / l0, inv1 = 1.0f / l1;
    const size_t row0 = (size_t)b * SEQ + qt * 128 + wid * 16 + (lane >> 2);
    const size_t row1 = row0 + 8;
    const int colB = h * D_K + (lane & 3) * 2;
    #pragma unroll
    for (int nt = 0; nt < 8; nt++) {
        const size_t c = colB + nt * 8;
        float v00 = o[nt][0] * inv0, v01 = o[nt][1] * inv0;
        float v10 = o[nt][2] * inv1, v11 = o[nt][3] * inv1;
        __nv_bfloat16 h00 = __float2bfloat16_rn(v00);
        __nv_bfloat16 h01 = __float2bfloat16_rn(v01);
        __nv_bfloat16 h10 = __float2bfloat16_rn(v10);
        __nv_bfloat16 h11 = __float2bfloat16_rn(v11);
        *(__nv_bfloat162*)(g_Ahi + row0 * D_MODEL + c) = __nv_bfloat162(h00, h01);
        *(__nv_bfloat162*)(g_Ahi + row1 * D_MODEL + c) = __nv_bfloat162(h10, h11);
        *(__nv_bfloat162*)(g_Alo + row0 * D_MODEL + c) = __nv_bfloat162(
            __float2bfloat16_rn(v00 - __bfloat162float(h00)),
            __float2bfloat16_rn(v01 - __bfloat162float(h01)));
        *(__nv_bfloat162*)(g_Alo + row1 * D_MODEL + c) = __nv_bfloat162(
            __float2bfloat16_rn(v10 - __bfloat162float(h10)),
            __float2bfloat16_rn(v11 - __bfloat162float(h11)));
    }
}

// ===================== launch ==============================================
extern "C" void kernel_launch(void* const* d_in, const int* in_sizes, int n_in,
                              void* d_out, int out_size)
{
    const float* q   = (const float*)d_in[0];
    const float* k   = (const float*)d_in[1];
    const float* v   = (const float*)d_in[2];
    const float* w_q = (const float*)d_in[3];
    const float* b_q = (const float*)d_in[4];
    const float* w_k = (const float*)d_in[5];
    const float* b_k = (const float*)d_in[6];
    const float* w_v = (const float*)d_in[7];
    const float* b_v = (const float*)d_in[8];
    const float* w_o = (const float*)d_in[9];
    const float* b_o = (const float*)d_in[10];
    float* out = (float*)d_out;

    cudaFuncSetAttribute(gemm_qkv, cudaFuncAttributeMaxDynamicSharedMemorySize, G_SMEM);
    cudaFuncSetAttribute(gemm_o,   cudaFuncAttributeMaxDynamicSharedMemorySize, G_SMEM);
    cudaFuncSetAttribute(attn_mma, cudaFuncAttributeMaxDynamicSharedMemorySize, ATTN_SMEM);

    const int n4 = XELEM / 4;

    wsplit_all<<<dim3(32, 32, 4), dim3(32, 8)>>>(w_q, w_k, w_v, w_o);
    split_all<<<dim3(n4 / 256, 3), 256>>>(q, k, v);

    gemm_qkv<<<dim3(D_MODEL / GBN, MROWS / GBM, 3), 256, G_SMEM>>>(b_q, b_k, b_v);

    attn_mma<<<dim3(SEQ / 128, N_HEAD * BATCH), 256, ATTN_SMEM>>>();

    gemm_o<<<dim3(D_MODEL / GBN, MROWS / GBM), 256, G_SMEM>>>(b_o, out);
}